// round 2
// baseline (speedup 1.0000x reference)
#include <cuda_runtime.h>

// Problem constants
#define PB 16
#define PD 256
#define PT 4096
#define PK 2048
#define PBT (PB * PT)          // 65536
#define NDEC (PB * PD * PT)    // 16777216
#define EPSV 1e-5f

// Scratch (allocation-free rule: __device__ globals)
__device__ float g_emb[PK * PD];   // 2 MB, L2-resident
__device__ float g_e2[PK];
__device__ int   g_codes[PBT];

// ---------------------------------------------------------------------------
// Kernel 1: emb[k,d] = embedding_sum[k,d] / max(usage[k], eps);  e2[k] = |emb_k|^2
// ---------------------------------------------------------------------------
__global__ void prep_kernel(const float* __restrict__ esum,
                            const float* __restrict__ cu) {
    int k = blockIdx.x;
    int d = threadIdx.x;                    // 256 threads = one d each
    float u = fmaxf(cu[k], EPSV);
    float v = __fdiv_rn(esum[k * PD + d], u);   // IEEE division (match jax)
    g_emb[k * PD + d] = v;

    __shared__ float red[256];
    red[d] = v * v;
    __syncthreads();
    #pragma unroll
    for (int s = 128; s > 0; s >>= 1) {
        if (d < s) red[d] += red[d + s];
        __syncthreads();
    }
    if (d == 0) g_e2[k] = red[0];
}

// ---------------------------------------------------------------------------
// Kernel 2: fused GEMM + argmin.
// Block = 64 t-rows x all 2048 k, looped in k-tiles of 128, d-chunks of 32.
// Thread (tx,ty) in 16x16 owns a 4t x 8k micro-tile of accumulators.
// score(t,k) = e2[k] - 2 * dot(x_t, emb_k)   (x2 and sqrt dropped: monotonic)
// ---------------------------------------------------------------------------
__global__ __launch_bounds__(256, 2)
void argmin_kernel(const float* __restrict__ x, float* __restrict__ codes_out) {
    __shared__ float xs[32][64];        // 8 KB   [d][t]
    __shared__ float es[128][33];       // 16.9 KB [k][d] (+1 pad: no bank conflicts)
    __shared__ float e2s[128];
    __shared__ float rmin[16][64];
    __shared__ int   ridx[16][64];

    const int tid = threadIdx.x;
    const int tx = tid & 15;
    const int ty = tid >> 4;
    const long t0 = (long)blockIdx.x * 64;      // global row in [0, BT)
    const int  b  = (int)(t0 >> 12);            // / 4096 (tile never crosses b)
    const int  tl = (int)(t0 & 4095);
    const float* xb = x + ((long)b * PD * PT + tl);

    float best[4];
    int   bidx[4];
    #pragma unroll
    for (int i = 0; i < 4; i++) { best[i] = 3.4e38f; bidx[i] = 0; }

    for (int k0 = 0; k0 < PK; k0 += 128) {
        float acc[4][8];
        #pragma unroll
        for (int i = 0; i < 4; i++)
            #pragma unroll
            for (int j = 0; j < 8; j++) acc[i][j] = 0.0f;

        for (int dc = 0; dc < PD; dc += 32) {
            __syncthreads();
            // load x tile: 32 d x 64 t (coalesced over t)
            #pragma unroll
            for (int r = 0; r < 8; r++) {
                int i = tid + r * 256;
                int d = i >> 6, t = i & 63;
                xs[d][t] = xb[(long)(dc + d) * PT + t];
            }
            // load emb tile: 128 k x 32 d (coalesced over d)
            #pragma unroll
            for (int r = 0; r < 16; r++) {
                int i = tid + r * 256;
                int kk = i >> 5, d = i & 31;
                es[kk][d] = g_emb[(k0 + kk) * PD + dc + d];
            }
            if (dc == 0 && tid < 128) e2s[tid] = g_e2[k0 + tid];
            __syncthreads();

            #pragma unroll
            for (int d = 0; d < 32; d++) {
                float4 xv = *(const float4*)&xs[d][tx * 4];
                float xr[4] = {xv.x, xv.y, xv.z, xv.w};
                #pragma unroll
                for (int j = 0; j < 8; j++) {
                    float e = es[ty * 8 + j][d];   // broadcast across tx
                    #pragma unroll
                    for (int i = 0; i < 4; i++)
                        acc[i][j] = fmaf(xr[i], e, acc[i][j]);
                }
            }
        }
        // epilogue: running argmin (k ascending within thread -> '<' keeps first)
        #pragma unroll
        for (int j = 0; j < 8; j++) {
            int   k  = k0 + ty * 8 + j;
            float e2 = e2s[ty * 8 + j];
            #pragma unroll
            for (int i = 0; i < 4; i++) {
                float s = fmaf(-2.0f, acc[i][j], e2);
                if (s < best[i]) { best[i] = s; bidx[i] = k; }
            }
        }
    }

    __syncthreads();
    #pragma unroll
    for (int i = 0; i < 4; i++) {
        rmin[ty][tx * 4 + i] = best[i];
        ridx[ty][tx * 4 + i] = bidx[i];
    }
    __syncthreads();
    if (tid < 64) {
        float bv = rmin[0][tid];
        int   bk = ridx[0][tid];
        #pragma unroll
        for (int y = 1; y < 16; y++) {
            float v = rmin[y][tid];
            int   kk = ridx[y][tid];
            if (v < bv || (v == bv && kk < bk)) { bv = v; bk = kk; }
        }
        g_codes[t0 + tid] = bk;
        if (codes_out) codes_out[t0 + tid] = (float)bk;
    }
}

// ---------------------------------------------------------------------------
// Kernel 3: decoded[b,d,t] = emb[code[b,t], d]   (coalesced writes, L2 gathers)
// ---------------------------------------------------------------------------
__global__ void decode_kernel(float* __restrict__ dec) {
    long idx = (long)blockIdx.x * 256 + threadIdx.x;   // < NDEC
    int t = (int)(idx & 4095);
    int d = (int)((idx >> 12) & 255);
    int b = (int)(idx >> 20);
    int code = g_codes[b * PT + t];
    dec[idx] = g_emb[code * PD + d];
}

__global__ void codes_int_kernel(int* __restrict__ out) {
    int i = blockIdx.x * 256 + threadIdx.x;
    if (i < PBT) out[i] = g_codes[i];
}

// ---------------------------------------------------------------------------
extern "C" void kernel_launch(void* const* d_in, const int* in_sizes, int n_in,
                              void* d_out, int out_size) {
    const float* x    = (const float*)d_in[0];
    const float* esum = (const float*)d_in[1];
    const float* cu   = (const float*)d_in[2];

    prep_kernel<<<PK, 256>>>(esum, cu);

    float* codes_out = nullptr;
    float* dec_out   = nullptr;
    bool   codes_as_int = false;

    if (out_size == PBT + NDEC) {            // [codes | decoded] as f32
        codes_out = (float*)d_out;
        dec_out   = (float*)d_out + PBT;
    } else if (out_size == NDEC) {           // decoded only
        dec_out = (float*)d_out;
    } else if (out_size == PBT) {            // codes only (likely int32)
        codes_as_int = true;
    } else {                                 // fallback: fill what fits
        codes_out = (float*)d_out;
        if (out_size >= PBT + NDEC) dec_out = (float*)d_out + PBT;
    }

    argmin_kernel<<<PBT / 64, 256>>>(x, codes_out);

    if (codes_as_int)
        codes_int_kernel<<<(PBT + 255) / 256, 256>>>((int*)d_out);
    if (dec_out)
        decode_kernel<<<NDEC / 256, 256>>>(dec_out);
}

// round 6
// speedup vs baseline: 1.5427x; 1.5427x over previous
#include <cuda_runtime.h>
#include <cuda_bf16.h>
#include <cstdint>

#define PB 16
#define PD 256
#define PT 4096
#define PK 2048
#define PBT (PB*PT)
#define NDEC (PB*PD*PT)
#define EPSV 1e-5f
#define THRESH_M 4e-3f

__device__ float g_emb[PK*PD];
__device__ float g_he2[PK];
__device__ int   g_codes[PBT];
__device__ __nv_bfloat16 g_x_s[2][(long)PBT*PD];
__device__ __nv_bfloat16 g_emb_s[2][PK*PD];
__device__ int g_flag[PBT];
__device__ int g_nflag;

__device__ __forceinline__ uint32_t smem_u32(const void* p){
    uint32_t a; asm("{ .reg .u64 t; cvta.to.shared.u64 t, %1; cvt.u32.u64 %0, t; }":"=r"(a):"l"(p)); return a; }
#define CPA(dst,src) asm volatile("cp.async.cg.shared.global [%0],[%1],16;"::"r"(dst),"l"(src):"memory")
#define CPC() asm volatile("cp.async.commit_group;":::"memory")
#define CPW1() asm volatile("cp.async.wait_group 1;":::"memory")
#define MMA(d,a,b0,b1) asm volatile( \
  "mma.sync.aligned.m16n8k16.row.col.f32.bf16.bf16.f32 {%0,%1,%2,%3},{%4,%5,%6,%7},{%8,%9},{%0,%1,%2,%3};" \
  : "+f"((d)[0]),"+f"((d)[1]),"+f"((d)[2]),"+f"((d)[3]) \
  : "r"((a)[0]),"r"((a)[1]),"r"((a)[2]),"r"((a)[3]),"r"(b0),"r"(b1))

// ---------- prep: emb = sum/clamp(usage); 2-way bf16 split; he2 = e2/2 ----------
__global__ void prep_emb_kernel(const float* __restrict__ es, const float* __restrict__ cu){
    int k=blockIdx.x, d=threadIdx.x;
    if(k==0 && d==0) g_nflag=0;
    float v = __fdiv_rn(es[k*PD+d], fmaxf(cu[k], EPSV));
    g_emb[k*PD+d]=v;
    __nv_bfloat16 h=__float2bfloat16(v);
    g_emb_s[0][k*PD+d]=h;
    g_emb_s[1][k*PD+d]=__float2bfloat16(v-__bfloat162float(h));
    __shared__ float red[256];
    red[d]=v*v; __syncthreads();
    #pragma unroll
    for(int s=128;s>0;s>>=1){ if(d<s) red[d]+=red[d+s]; __syncthreads(); }
    if(d==0) g_he2[k]=0.5f*red[0];
}

// ---------- prep: x [B,D,T] -> [bt][d] bf16 2-way splits ----------
__global__ void prep_x_kernel(const float* __restrict__ x){
    __shared__ float sm[64][65];
    int t0=blockIdx.x*64, d0=blockIdx.y*64, b=blockIdx.z, tid=threadIdx.x;
    #pragma unroll
    for(int r=0;r<16;r++){ int i=tid+r*256; sm[i>>6][i&63] = x[((long)(b*PD+d0+(i>>6)))*PT + t0+(i&63)]; }
    __syncthreads();
    #pragma unroll
    for(int r=0;r<16;r++){
        int i=tid+r*256, t=i>>6, d=i&63;
        float v=sm[d][t];
        long o=(long)(b*PT+t0+t)*PD + d0+d;
        __nv_bfloat16 h=__float2bfloat16(v);
        g_x_s[0][o]=h;
        g_x_s[1][o]=__float2bfloat16(v-__bfloat162float(h));
    }
}

// ---------- main: HMMA bf16-split GEMM + fused argmin ----------
#define SXO 0
#define SEO 135168
#define SHE 208896
#define SRD 217088
#define SMEMB 218624

__global__ void __launch_bounds__(256,1)
argmin_mma_kernel(){
    extern __shared__ char smem[];
    uint32_t sb = smem_u32(smem);
    const int tid=threadIdx.x, lane=tid&31, wid=tid>>5;
    const int wm=wid&3, wn=wid>>2, lr=lane>>2, lc=lane&3;
    const int row0=blockIdx.x*128;
    float* she2all=(float*)(smem+SHE);
    float* sb1=(float*)(smem+SRD); float* sb2=sb1+128; int* sk=(int*)(sb2+128);

    // resident x splits: 2 x [128 rows x 512B] (row stride 528)
    #pragma unroll 4
    for(int r=0;r<32;r++){ int id=r*256+tid; int sp=id>>12, row=(id>>5)&127, c=id&31;
        CPA(sb+SXO+sp*67584+row*528+c*16, g_x_s[sp]+(((long)(row0+row))<<8)+c*8); }
    CPC();
    // emb chunk 0 into stage buffer 0
    #pragma unroll
    for(int j=0;j<8;j++){ int id=j*256+tid; int sp=id>>10, row=(id>>3)&127, c=id&7;
        CPA(sb+SEO+sp*18432+row*144+c*16, g_emb_s[sp]+((long)row<<8)+c*8); }
    CPC();
    #pragma unroll
    for(int j=0;j<8;j++) she2all[j*256+tid]=g_he2[j*256+tid];

    float b1v[4], b2v[4]; int bkv[4];
    #pragma unroll
    for(int i=0;i<4;i++){ b1v[i]=-3.4e38f; b2v[i]=-3.4e38f; bkv[i]=0; }

    for(int kt=0;kt<16;kt++){
        float acc[2][8][4];
        #pragma unroll
        for(int a=0;a<2;a++)
            #pragma unroll
            for(int b=0;b<8;b++)
                #pragma unroll
                for(int c=0;c<4;c++) acc[a][b][c]=0.f;
        for(int dc=0;dc<4;dc++){
            int s=kt*4+dc;
            __syncthreads();
            if(s+1<64){
                int ns=s+1, nk=ns>>2, nd=ns&3, nb=ns&1;
                #pragma unroll
                for(int j=0;j<8;j++){ int id=j*256+tid; int sp=id>>10, row=(id>>3)&127, c=id&7;
                    CPA(sb+SEO+nb*36864+sp*18432+row*144+c*16,
                        g_emb_s[sp]+(((long)(nk*128+row))<<8)+nd*64+c*8); }
            }
            CPC(); CPW1();
            __syncthreads();
            const char* eb = smem + SEO + (s&1)*36864;
            #pragma unroll
            for(int ks=0;ks<4;ks++){
                uint32_t ah[2][4], al[2][4];
                #pragma unroll
                for(int mt=0;mt<2;mt++){
                    // FIX: + dc*128 — select this k-iteration's 64-d quarter of the resident A tile
                    const char* pa = smem + SXO + (wm*32+mt*16+lr)*528 + dc*128 + ks*32 + lc*4;
                    ah[mt][0]=*(const uint32_t*)pa;            ah[mt][1]=*(const uint32_t*)(pa+8*528);
                    ah[mt][2]=*(const uint32_t*)(pa+16);       ah[mt][3]=*(const uint32_t*)(pa+8*528+16);
                    al[mt][0]=*(const uint32_t*)(pa+67584);    al[mt][1]=*(const uint32_t*)(pa+67584+8*528);
                    al[mt][2]=*(const uint32_t*)(pa+67584+16); al[mt][3]=*(const uint32_t*)(pa+67584+8*528+16);
                }
                #pragma unroll
                for(int nt=0;nt<8;nt++){
                    const char* pb = eb + (wn*64+nt*8+lr)*144 + ks*32 + lc*4;
                    uint32_t bh0=*(const uint32_t*)pb,         bh1=*(const uint32_t*)(pb+16);
                    uint32_t bl0=*(const uint32_t*)(pb+18432), bl1=*(const uint32_t*)(pb+18432+16);
                    #pragma unroll
                    for(int mt=0;mt<2;mt++){
                        MMA(acc[mt][nt], ah[mt], bh0, bh1);
                        MMA(acc[mt][nt], ah[mt], bl0, bl1);
                        MMA(acc[mt][nt], al[mt], bh0, bh1);
                    }
                }
            }
        }
        // epilogue: v = dot - he2, maximize, track best-2 (k ascending)
        #pragma unroll
        for(int nt=0;nt<8;nt++){
            int kb = wn*64 + nt*8 + lc*2;
            float hea = she2all[kt*128+kb], heb = she2all[kt*128+kb+1];
            int k0 = kt*128 + kb;
            #pragma unroll
            for(int mt=0;mt<2;mt++)
                #pragma unroll
                for(int h=0;h<2;h++){
                    int idx=mt*2+h;
                    float v0 = acc[mt][nt][2*h+0]-hea;
                    float v1 = acc[mt][nt][2*h+1]-heb;
                    if(v0>b1v[idx]){ b2v[idx]=b1v[idx]; b1v[idx]=v0; bkv[idx]=k0; }
                    else if(v0>b2v[idx]) b2v[idx]=v0;
                    if(v1>b1v[idx]){ b2v[idx]=b1v[idx]; b1v[idx]=v1; bkv[idx]=k0+1; }
                    else if(v1>b2v[idx]) b2v[idx]=v1;
                }
        }
    }
    // merge across lc (4 lanes of same row group)
    #pragma unroll
    for(int off=1;off<4;off<<=1)
        #pragma unroll
        for(int i=0;i<4;i++){
            float ob1=__shfl_xor_sync(0xffffffffu,b1v[i],off);
            float ob2=__shfl_xor_sync(0xffffffffu,b2v[i],off);
            int obk=__shfl_xor_sync(0xffffffffu,bkv[i],off);
            if(ob1>b1v[i]){ b2v[i]=fmaxf(b1v[i],ob2); b1v[i]=ob1; bkv[i]=obk; }
            else b2v[i]=fmaxf(b2v[i],ob1);
        }
    // cross-warp merge (wn=1 -> smem; wn=0 merges + writes)
    if(wn==1 && lc==0){
        #pragma unroll
        for(int i=0;i<4;i++){ int r=wm*32+(i>>1)*16+(i&1)*8+lr; sb1[r]=b1v[i]; sb2[r]=b2v[i]; sk[r]=bkv[i]; }
    }
    __syncthreads();
    if(wn==0 && lc==0){
        #pragma unroll
        for(int i=0;i<4;i++){
            int r=wm*32+(i>>1)*16+(i&1)*8+lr;
            float ob1=sb1[r], ob2=sb2[r]; int obk=sk[r];
            if(ob1>b1v[i]){ b2v[i]=fmaxf(b1v[i],ob2); b1v[i]=ob1; bkv[i]=obk; }
            else b2v[i]=fmaxf(b2v[i],ob1);
            int row=row0+r;
            g_codes[row]=bkv[i];
            if(b1v[i]-b2v[i] < THRESH_M){ int p=atomicAdd(&g_nflag,1); g_flag[p]=row; }
        }
    }
}

// ---------- batched exact fp32 recheck ----------
__global__ void __launch_bounds__(256,1) recheck_kernel(const float* __restrict__ x){
    extern __shared__ char smem[];
    float* xs  = (float*)smem;               // [256][64]
    float* es  = xs + 256*64;                // [128][33]
    float* rmin= es + 128*33;                // [16][64]
    int*  ridx = (int*)(rmin + 16*64);
    float* she = (float*)(ridx + 16*64);     // [128]
    int*  srows= (int*)(she + 128);          // [64]
    int tid=threadIdx.x, tx=tid&15, ty=tid>>4;
    int n=g_nflag;
    for(int base=blockIdx.x*64; base<n; base+=gridDim.x*64){
        int cnt=min(64,n-base);
        if(tid<64) srows[tid]=g_flag[base+min(tid,cnt-1)];
        __syncthreads();
        for(int i=0;i<64;i++){ int row=srows[i]; int b=row>>12,t=row&4095;
            xs[tid*64+i]=x[(((long)(b*PD+tid))<<12)+t]; }
        __syncthreads();
        float best[4]; int bidx[4];
        #pragma unroll
        for(int i=0;i<4;i++){ best[i]=-3.4e38f; bidx[i]=1<<30; }
        for(int k0=0;k0<PK;k0+=128){
            if(tid<128) she[tid]=g_he2[k0+tid];
            float accr[4][8];
            #pragma unroll
            for(int i=0;i<4;i++)
                #pragma unroll
                for(int j=0;j<8;j++) accr[i][j]=0.f;
            for(int dcB=0;dcB<8;dcB++){
                __syncthreads();
                #pragma unroll
                for(int r=0;r<16;r++){ int i=tid+r*256; es[(i>>5)*33+(i&31)]=g_emb[(k0+(i>>5))*PD+dcB*32+(i&31)]; }
                __syncthreads();
                #pragma unroll
                for(int d=0;d<32;d++){
                    float4 xv=*(const float4*)&xs[(dcB*32+d)*64+tx*4];
                    float xr[4]={xv.x,xv.y,xv.z,xv.w};
                    #pragma unroll
                    for(int j=0;j<8;j++){ float e=es[(ty*8+j)*33+d];
                        #pragma unroll
                        for(int i=0;i<4;i++) accr[i][j]=fmaf(xr[i],e,accr[i][j]); }
                }
            }
            #pragma unroll
            for(int j=0;j<8;j++){ int k=k0+ty*8+j; float he=she[ty*8+j];
                #pragma unroll
                for(int i=0;i<4;i++){ float v=accr[i][j]-he;
                    if(v>best[i]||(v==best[i]&&k<bidx[i])){ best[i]=v; bidx[i]=k; } } }
        }
        __syncthreads();
        #pragma unroll
        for(int i=0;i<4;i++){ rmin[ty*64+tx*4+i]=best[i]; ridx[ty*64+tx*4+i]=bidx[i]; }
        __syncthreads();
        if(tid<64){
            float bv=rmin[tid]; int bk=ridx[tid];
            #pragma unroll
            for(int y=1;y<16;y++){ float v=rmin[y*64+tid]; int kk=ridx[y*64+tid];
                if(v>bv||(v==bv&&kk<bk)){ bv=v; bk=kk; } }
            if(tid<cnt) g_codes[srows[tid]]=bk;
        }
        __syncthreads();
    }
}

// ---------- outputs ----------
__global__ void emit_codes_f_kernel(float* o){ int i=blockIdx.x*256+threadIdx.x; o[i]=(float)g_codes[i]; }
__global__ void emit_codes_i_kernel(int* o){ int i=blockIdx.x*256+threadIdx.x; o[i]=g_codes[i]; }
__global__ void decode_kernel(float* __restrict__ dec){
    long idx=(long)blockIdx.x*256+threadIdx.x;
    int t=(int)(idx&4095), d=(int)((idx>>12)&255), b=(int)(idx>>20);
    dec[idx]=g_emb[g_codes[b*PT+t]*PD+d];
}

extern "C" void kernel_launch(void* const* d_in, const int* in_sizes, int n_in,
                              void* d_out, int out_size){
    const float* x=(const float*)d_in[0];
    const float* esum=(const float*)d_in[1];
    const float* cu=(const float*)d_in[2];

    prep_emb_kernel<<<PK,256>>>(esum,cu);
    prep_x_kernel<<<dim3(64,4,16),256>>>(x);

    cudaFuncSetAttribute(argmin_mma_kernel,cudaFuncAttributeMaxDynamicSharedMemorySize,SMEMB);
    cudaFuncSetAttribute(recheck_kernel,cudaFuncAttributeMaxDynamicSharedMemorySize,95000);
    argmin_mma_kernel<<<PBT/128,256,SMEMB>>>();
    recheck_kernel<<<128,256,95000>>>(x);

    float* codes_out=nullptr; float* dec_out=nullptr; bool ci=false;
    if(out_size==PBT+NDEC){ codes_out=(float*)d_out; dec_out=(float*)d_out+PBT; }
    else if(out_size==NDEC){ dec_out=(float*)d_out; }
    else if(out_size==PBT){ ci=true; }
    else { codes_out=(float*)d_out; if(out_size>=PBT+NDEC) dec_out=(float*)d_out+PBT; }

    if(codes_out) emit_codes_f_kernel<<<PBT/256,256>>>(codes_out);
    if(ci)        emit_codes_i_kernel<<<PBT/256,256>>>((int*)d_out);
    if(dec_out)   decode_kernel<<<NDEC/256,256>>>(dec_out);
}

// round 7
// speedup vs baseline: 1.8026x; 1.1684x over previous
#include <cuda_runtime.h>
#include <cuda_bf16.h>
#include <cstdint>

#define PB 16
#define PD 256
#define PT 4096
#define PK 2048
#define PBT (PB*PT)
#define NDEC (PB*PD*PT)
#define EPSV 1e-5f
#define THRESH_M 1.5e-3f

__device__ float g_emb[PK*PD];
__device__ float g_he2[PK];
__device__ int   g_codes[PBT];
__device__ __nv_bfloat16 g_x_s[2][(long)PBT*PD];
__device__ __nv_bfloat16 g_emb_s[2][PK*PD];
__device__ int g_flag[PBT];
__device__ int g_nflag;
__device__ unsigned long long g_best[PBT];

__device__ __forceinline__ uint32_t smem_u32(const void* p){
    uint32_t a; asm("{ .reg .u64 t; cvta.to.shared.u64 t, %1; cvt.u32.u64 %0, t; }":"=r"(a):"l"(p)); return a; }
#define CPA(dst,src) asm volatile("cp.async.cg.shared.global [%0],[%1],16;"::"r"(dst),"l"(src):"memory")
#define CPC() asm volatile("cp.async.commit_group;":::"memory")
#define CPW1() asm volatile("cp.async.wait_group 1;":::"memory")
#define MMA(d,a,b0,b1) asm volatile( \
  "mma.sync.aligned.m16n8k16.row.col.f32.bf16.bf16.f32 {%0,%1,%2,%3},{%4,%5,%6,%7},{%8,%9},{%0,%1,%2,%3};" \
  : "+f"((d)[0]),"+f"((d)[1]),"+f"((d)[2]),"+f"((d)[3]) \
  : "r"((a)[0]),"r"((a)[1]),"r"((a)[2]),"r"((a)[3]),"r"(b0),"r"(b1))
#define LDSM4(r0,r1,r2,r3,addr) asm volatile( \
  "ldmatrix.sync.aligned.m8n8.x4.shared.b16 {%0,%1,%2,%3},[%4];" \
  : "=r"(r0),"=r"(r1),"=r"(r2),"=r"(r3) : "r"(addr))

// ---------- prep ----------
__global__ void prep_emb_kernel(const float* __restrict__ es, const float* __restrict__ cu){
    int k=blockIdx.x, d=threadIdx.x;
    if(k==0 && d==0) g_nflag=0;
    float v = __fdiv_rn(es[k*PD+d], fmaxf(cu[k], EPSV));
    g_emb[k*PD+d]=v;
    __nv_bfloat16 h=__float2bfloat16(v);
    g_emb_s[0][k*PD+d]=h;
    g_emb_s[1][k*PD+d]=__float2bfloat16(v-__bfloat162float(h));
    __shared__ float red[256];
    red[d]=v*v; __syncthreads();
    #pragma unroll
    for(int s=128;s>0;s>>=1){ if(d<s) red[d]+=red[d+s]; __syncthreads(); }
    if(d==0) g_he2[k]=0.5f*red[0];
}

__global__ void prep_x_kernel(const float* __restrict__ x){
    __shared__ float sm[64][65];
    int t0=blockIdx.x*64, d0=blockIdx.y*64, b=blockIdx.z, tid=threadIdx.x;
    #pragma unroll
    for(int r=0;r<16;r++){ int i=tid+r*256; sm[i>>6][i&63] = x[((long)(b*PD+d0+(i>>6)))*PT + t0+(i&63)]; }
    __syncthreads();
    #pragma unroll
    for(int r=0;r<16;r++){
        int i=tid+r*256, t=i>>6, d=i&63;
        float v=sm[d][t];
        long o=(long)(b*PT+t0+t)*PD + d0+d;
        __nv_bfloat16 h=__float2bfloat16(v);
        g_x_s[0][o]=h;
        g_x_s[1][o]=__float2bfloat16(v-__bfloat162float(h));
    }
}

// ---------- main: HMMA + ldmatrix + fused argmin ----------
#define SXO 0
#define SEO 135168
#define SHE 208896
#define SRD 217088
#define SMEMB 218624

__global__ void __launch_bounds__(256,1)
argmin_mma_kernel(){
    extern __shared__ char smem[];
    uint32_t sb = smem_u32(smem);
    const int tid=threadIdx.x, lane=tid&31, wid=tid>>5;
    const int wm=wid&3, wn=wid>>2, lr=lane>>2, lc=lane&3;
    const int row0=blockIdx.x*128;
    const int lrow=lane&15, lkoff=(lane>>4)*16;
    float* she2all=(float*)(smem+SHE);
    float* sb1=(float*)(smem+SRD); float* sb2=sb1+128; int* sk=(int*)(sb2+128);

    #pragma unroll 4
    for(int r=0;r<32;r++){ int id=r*256+tid; int sp=id>>12, row=(id>>5)&127, c=id&31;
        CPA(sb+SXO+sp*67584+row*528+c*16, g_x_s[sp]+(((long)(row0+row))<<8)+c*8); }
    CPC();
    #pragma unroll
    for(int j=0;j<8;j++){ int id=j*256+tid; int sp=id>>10, row=(id>>3)&127, c=id&7;
        CPA(sb+SEO+sp*18432+row*144+c*16, g_emb_s[sp]+((long)row<<8)+c*8); }
    CPC();
    #pragma unroll
    for(int j=0;j<8;j++) she2all[j*256+tid]=g_he2[j*256+tid];

    float b1v[4], b2v[4]; int bkv[4];
    #pragma unroll
    for(int i=0;i<4;i++){ b1v[i]=-3.4e38f; b2v[i]=-3.4e38f; bkv[i]=0; }

    for(int kt=0;kt<16;kt++){
        float acc[2][8][4];
        #pragma unroll
        for(int a=0;a<2;a++)
            #pragma unroll
            for(int b=0;b<8;b++)
                #pragma unroll
                for(int c=0;c<4;c++) acc[a][b][c]=0.f;
        for(int dc=0;dc<4;dc++){
            int s=kt*4+dc;
            __syncthreads();
            if(s+1<64){
                int ns=s+1, nk=ns>>2, nd=ns&3, nb=ns&1;
                #pragma unroll
                for(int j=0;j<8;j++){ int id=j*256+tid; int sp=id>>10, row=(id>>3)&127, c=id&7;
                    CPA(sb+SEO+nb*36864+sp*18432+row*144+c*16,
                        g_emb_s[sp]+(((long)(nk*128+row))<<8)+nd*64+c*8); }
            }
            CPC(); CPW1();
            __syncthreads();
            uint32_t ebu = sb + SEO + (s&1)*36864;
            #pragma unroll
            for(int ks=0;ks<4;ks++){
                uint32_t ah[2][4], al[2][4];
                #pragma unroll
                for(int mt=0;mt<2;mt++){
                    uint32_t aa = sb + SXO + (wm*32+mt*16+lrow)*528 + dc*128 + ks*32 + lkoff;
                    LDSM4(ah[mt][0],ah[mt][1],ah[mt][2],ah[mt][3], aa);
                    LDSM4(al[mt][0],al[mt][1],al[mt][2],al[mt][3], aa+67584);
                }
                #pragma unroll
                for(int p=0;p<4;p++){
                    uint32_t ba = ebu + (wn*64+p*16+lrow)*144 + ks*32 + lkoff;
                    uint32_t h0,h1,h2,h3,l0,l1,l2,l3;
                    LDSM4(h0,h1,h2,h3, ba);
                    LDSM4(l0,l1,l2,l3, ba+18432);
                    #pragma unroll
                    for(int mt=0;mt<2;mt++){
                        MMA(acc[mt][2*p],   ah[mt], h0, h2);
                        MMA(acc[mt][2*p],   al[mt], h0, h2);
                        MMA(acc[mt][2*p],   ah[mt], l0, l2);
                        MMA(acc[mt][2*p+1], ah[mt], h1, h3);
                        MMA(acc[mt][2*p+1], al[mt], h1, h3);
                        MMA(acc[mt][2*p+1], ah[mt], l1, l3);
                    }
                }
            }
        }
        #pragma unroll
        for(int nt=0;nt<8;nt++){
            int kb = wn*64 + nt*8 + lc*2;
            float hea = she2all[kt*128+kb], heb = she2all[kt*128+kb+1];
            int k0 = kt*128 + kb;
            #pragma unroll
            for(int mt=0;mt<2;mt++)
                #pragma unroll
                for(int h=0;h<2;h++){
                    int idx=mt*2+h;
                    float v0 = acc[mt][nt][2*h+0]-hea;
                    float v1 = acc[mt][nt][2*h+1]-heb;
                    if(v0>b1v[idx]){ b2v[idx]=b1v[idx]; b1v[idx]=v0; bkv[idx]=k0; }
                    else if(v0>b2v[idx]) b2v[idx]=v0;
                    if(v1>b1v[idx]){ b2v[idx]=b1v[idx]; b1v[idx]=v1; bkv[idx]=k0+1; }
                    else if(v1>b2v[idx]) b2v[idx]=v1;
                }
        }
    }
    #pragma unroll
    for(int off=1;off<4;off<<=1)
        #pragma unroll
        for(int i=0;i<4;i++){
            float ob1=__shfl_xor_sync(0xffffffffu,b1v[i],off);
            float ob2=__shfl_xor_sync(0xffffffffu,b2v[i],off);
            int obk=__shfl_xor_sync(0xffffffffu,bkv[i],off);
            if(ob1>b1v[i]){ b2v[i]=fmaxf(b1v[i],ob2); b1v[i]=ob1; bkv[i]=obk; }
            else b2v[i]=fmaxf(b2v[i],ob1);
        }
    if(wn==1 && lc==0){
        #pragma unroll
        for(int i=0;i<4;i++){ int r=wm*32+(i>>1)*16+(i&1)*8+lr; sb1[r]=b1v[i]; sb2[r]=b2v[i]; sk[r]=bkv[i]; }
    }
    __syncthreads();
    if(wn==0 && lc==0){
        #pragma unroll
        for(int i=0;i<4;i++){
            int r=wm*32+(i>>1)*16+(i&1)*8+lr;
            float ob1=sb1[r], ob2=sb2[r]; int obk=sk[r];
            if(ob1>b1v[i]){ b2v[i]=fmaxf(b1v[i],ob2); b1v[i]=ob1; bkv[i]=obk; }
            else b2v[i]=fmaxf(b2v[i],ob1);
            int row=row0+r;
            g_codes[row]=bkv[i];
            if(b1v[i]-b2v[i] < THRESH_M){ int p=atomicAdd(&g_nflag,1); g_flag[p]=row; }
        }
    }
}

// ---------- recheck: init keys, 4-way k-sliced exact fp32, finalize ----------
__global__ void recheck_init_kernel(){
    int i=blockIdx.x*256+threadIdx.x;
    if(i<g_nflag) g_best[g_flag[i]]=~0ull;
}

__global__ void __launch_bounds__(256,1) recheck_kernel(const float* __restrict__ x){
    extern __shared__ char smem[];
    float* xs  = (float*)smem;               // [256][32]
    float* es  = xs + 256*32;                // [128][33]
    float* rv  = es + 128*33;                // [32 ty][32 row]
    int*   rk  = (int*)(rv + 32*32);
    float* she = (float*)(rk + 32*32);       // [128]
    int*  srows= (int*)(she + 128);          // [32]
    int tid=threadIdx.x, tx=tid&7, ty=tid>>3;
    int ksl=blockIdx.y;                      // 0..3 -> k slice of 512
    int n=g_nflag;
    for(int base=blockIdx.x*32; base<n; base+=gridDim.x*32){
        int cnt=min(32,n-base);
        if(tid<32) srows[tid]=g_flag[base+min(tid,cnt-1)];
        __syncthreads();
        // load 32 rows x 256 d (xs[d][i])
        for(int r=0;r<32;r++){ int i=tid&31; int d=(tid>>5)+(r<<3);
            int row=srows[i]; int b=row>>12,t=row&4095;
            xs[d*32+i]=x[(((long)(b*PD+d))<<12)+t]; }
        __syncthreads();
        float best=-3.4e38f; int bidx=1<<30;
        float accr[4][4];
        for(int kt=0;kt<4;kt++){
            int k0 = ksl*512 + kt*128;
            if(tid<128) she[tid]=g_he2[k0+tid];
            #pragma unroll
            for(int i=0;i<4;i++)
                #pragma unroll
                for(int j=0;j<4;j++) accr[i][j]=0.f;
            for(int dcB=0;dcB<8;dcB++){
                __syncthreads();
                #pragma unroll
                for(int r=0;r<16;r++){ int i=tid+r*256; es[(i>>5)*33+(i&31)]=g_emb[(k0+(i>>5))*PD+dcB*32+(i&31)]; }
                __syncthreads();
                #pragma unroll
                for(int d=0;d<32;d++){
                    float4 xv=*(const float4*)&xs[(dcB*32+d)*32+tx*4];
                    float xr[4]={xv.x,xv.y,xv.z,xv.w};
                    #pragma unroll
                    for(int j=0;j<4;j++){ float e=es[(ty*4+j)*33+d];
                        #pragma unroll
                        for(int i=0;i<4;i++) accr[i][j]=fmaf(xr[i],e,accr[i][j]); }
                }
            }
            __syncthreads();
            // per-thread best over its 4 k for its 4 rows -> store per (ty,row)
            #pragma unroll
            for(int i=0;i<4;i++){
                float bb=-3.4e38f; int bk=1<<30;
                #pragma unroll
                for(int j=0;j<4;j++){ int k=k0+ty*4+j; float v=accr[i][j]-she[ty*4+j];
                    if(v>bb||(v==bb&&k<bk)){ bb=v; bk=bk=k; } }
                if(kt==0){ rv[ty*32+tx*4+i]=bb; rk[ty*32+tx*4+i]=bk; }
                else { float ov=rv[ty*32+tx*4+i]; int ok=rk[ty*32+tx*4+i];
                       if(bb>ov||(bb==ov&&bk<ok)){ rv[ty*32+tx*4+i]=bb; rk[ty*32+tx*4+i]=bk; } }
            }
        }
        __syncthreads();
        if(tid<32){
            float bv=rv[tid]; int bk=rk[tid];
            #pragma unroll
            for(int y=1;y<32;y++){ float v=rv[y*32+tid]; int kk=rk[y*32+tid];
                if(v>bv||(v==bv&&kk<bk)){ bv=v; bk=kk; } }
            if(tid<cnt){
                float s=-bv;                       // minimize he2-dot
                uint32_t bits=__float_as_uint(s);
                uint32_t ord = bits ^ ((bits>>31) ? 0xFFFFFFFFu : 0x80000000u);
                unsigned long long key = ((unsigned long long)ord<<32) | (uint32_t)bk;
                atomicMin(&g_best[srows[tid]], key);
            }
        }
        __syncthreads();
    }
}

__global__ void recheck_final_kernel(){
    int i=blockIdx.x*256+threadIdx.x;
    if(i<g_nflag){ int row=g_flag[i]; g_codes[row]=(int)(g_best[row]&0xFFFFFFFFull); }
}

// ---------- outputs ----------
__global__ void emit_codes_f_kernel(float* o){ int i=blockIdx.x*256+threadIdx.x; o[i]=(float)g_codes[i]; }
__global__ void emit_codes_i_kernel(int* o){ int i=blockIdx.x*256+threadIdx.x; o[i]=g_codes[i]; }
__global__ void decode_kernel(float* __restrict__ dec){
    long idx=(long)blockIdx.x*256+threadIdx.x;
    int t=(int)(idx&4095), d=(int)((idx>>12)&255), b=(int)(idx>>20);
    dec[idx]=g_emb[g_codes[b*PT+t]*PD+d];
}

extern "C" void kernel_launch(void* const* d_in, const int* in_sizes, int n_in,
                              void* d_out, int out_size){
    const float* x=(const float*)d_in[0];
    const float* esum=(const float*)d_in[1];
    const float* cu=(const float*)d_in[2];

    prep_emb_kernel<<<PK,256>>>(esum,cu);
    prep_x_kernel<<<dim3(64,4,16),256>>>(x);

    cudaFuncSetAttribute(argmin_mma_kernel,cudaFuncAttributeMaxDynamicSharedMemorySize,SMEMB);
    cudaFuncSetAttribute(recheck_kernel,cudaFuncAttributeMaxDynamicSharedMemorySize,65536);
    argmin_mma_kernel<<<PBT/128,256,SMEMB>>>();
    recheck_init_kernel<<<PBT/256,256>>>();
    recheck_kernel<<<dim3(192,4),256,65536>>>(x);
    recheck_final_kernel<<<PBT/256,256>>>();

    float* codes_out=nullptr; float* dec_out=nullptr; bool ci=false;
    if(out_size==PBT+NDEC){ codes_out=(float*)d_out; dec_out=(float*)d_out+PBT; }
    else if(out_size==NDEC){ dec_out=(float*)d_out; }
    else if(out_size==PBT){ ci=true; }
    else { codes_out=(float*)d_out; if(out_size>=PBT+NDEC) dec_out=(float*)d_out+PBT; }

    if(codes_out) emit_codes_f_kernel<<<PBT/256,256>>>(codes_out);
    if(ci)        emit_codes_i_kernel<<<PBT/256,256>>>((int*)d_out);
    if(dec_out)   decode_kernel<<<NDEC/256,256>>>(dec_out);
}

// round 8
// speedup vs baseline: 2.8359x; 1.5732x over previous
#include <cuda_runtime.h>
#include <cuda_bf16.h>
#include <cstdint>

#define PB 16
#define PD 256
#define PT 4096
#define PK 2048
#define PBT (PB*PT)
#define NDEC (PB*PD*PT)
#define EPSV 1e-5f
#define THRESH_M 0.25f

__device__ float g_emb[PK*PD];
__device__ float g_he2[PK];
__device__ int   g_codes[PBT];
__device__ __nv_bfloat16 g_x_h[(long)PBT*PD];
__device__ __nv_bfloat16 g_emb_h[PK*PD];
__device__ int g_flag[PBT];
__device__ int g_nflag;
__device__ unsigned long long g_best[PBT];

__device__ __forceinline__ uint32_t smem_u32(const void* p){
    uint32_t a; asm("{ .reg .u64 t; cvta.to.shared.u64 t, %1; cvt.u32.u64 %0, t; }":"=r"(a):"l"(p)); return a; }
#define CPA(dst,src) asm volatile("cp.async.cg.shared.global [%0],[%1],16;"::"r"(dst),"l"(src):"memory")
#define CPC() asm volatile("cp.async.commit_group;":::"memory")
#define CPW1() asm volatile("cp.async.wait_group 1;":::"memory")
#define MMA(d,a,b0,b1) asm volatile( \
  "mma.sync.aligned.m16n8k16.row.col.f32.bf16.bf16.f32 {%0,%1,%2,%3},{%4,%5,%6,%7},{%8,%9},{%0,%1,%2,%3};" \
  : "+f"((d)[0]),"+f"((d)[1]),"+f"((d)[2]),"+f"((d)[3]) \
  : "r"((a)[0]),"r"((a)[1]),"r"((a)[2]),"r"((a)[3]),"r"(b0),"r"(b1))
#define LDSM4(r0,r1,r2,r3,addr) asm volatile( \
  "ldmatrix.sync.aligned.m8n8.x4.shared.b16 {%0,%1,%2,%3},[%4];" \
  : "=r"(r0),"=r"(r1),"=r"(r2),"=r"(r3) : "r"(addr))

// ---------- prep ----------
__global__ void prep_emb_kernel(const float* __restrict__ es, const float* __restrict__ cu){
    int k=blockIdx.x, d=threadIdx.x;
    if(k==0 && d==0) g_nflag=0;
    float v = __fdiv_rn(es[k*PD+d], fmaxf(cu[k], EPSV));
    g_emb[k*PD+d]=v;
    g_emb_h[k*PD+d]=__float2bfloat16(v);
    __shared__ float red[256];
    red[d]=v*v; __syncthreads();
    #pragma unroll
    for(int s=128;s>0;s>>=1){ if(d<s) red[d]+=red[d+s]; __syncthreads(); }
    if(d==0) g_he2[k]=0.5f*red[0];
}

__global__ void prep_x_kernel(const float* __restrict__ x){
    __shared__ float sm[64][65];
    int t0=blockIdx.x*64, d0=blockIdx.y*64, b=blockIdx.z, tid=threadIdx.x;
    #pragma unroll
    for(int r=0;r<16;r++){ int i=tid+r*256; sm[i>>6][i&63] = x[((long)(b*PD+d0+(i>>6)))*PT + t0+(i&63)]; }
    __syncthreads();
    #pragma unroll
    for(int r=0;r<16;r++){
        int i=tid+r*256, t=i>>6, d=i&63;
        long o=(long)(b*PT+t0+t)*PD + d0+d;
        g_x_h[o]=__float2bfloat16(sm[d][t]);
    }
}

// ---------- main: single-product bf16 HMMA + fused argmin ----------
// smem: A 128x528 = 67584 | B 2x(128x144) = 36864 @67584 | she2 8KB @104448 |
//       red 1536 @112640  -> total 114176
#define SEO 67584
#define SHE 104448
#define SRD 112640
#define SMEMB 114176

__global__ void __launch_bounds__(256,1)
argmin_mma_kernel(){
    extern __shared__ char smem[];
    uint32_t sb = smem_u32(smem);
    const int tid=threadIdx.x, lane=tid&31, wid=tid>>5;
    const int wm=wid&3, wn=wid>>2, lr=lane>>2, lc=lane&3;
    const int row0=blockIdx.x*128;
    const int lrow=lane&15, lkoff=(lane>>4)*16;
    float* she2all=(float*)(smem+SHE);
    float* sb1=(float*)(smem+SRD); float* sb2=sb1+128; int* sk=(int*)(sb2+128);

    // resident x (bf16): 128 rows x 512B (stride 528)
    #pragma unroll 4
    for(int r=0;r<16;r++){ int id=r*256+tid; int row=id>>5, c=id&31;
        CPA(sb+row*528+c*16, g_x_h+(((long)(row0+row))<<8)+c*8); }
    CPC();
    // emb chunk 0 -> stage 0
    #pragma unroll
    for(int j=0;j<4;j++){ int id=j*256+tid; int row=id>>3, c=id&7;
        CPA(sb+SEO+row*144+c*16, g_emb_h+((long)row<<8)+c*8); }
    CPC();
    #pragma unroll
    for(int j=0;j<8;j++) she2all[j*256+tid]=g_he2[j*256+tid];

    float b1v[4], b2v[4]; int bkv[4];
    #pragma unroll
    for(int i=0;i<4;i++){ b1v[i]=-3.4e38f; b2v[i]=-3.4e38f; bkv[i]=0; }

    for(int kt=0;kt<16;kt++){
        float acc[2][8][4];
        #pragma unroll
        for(int a=0;a<2;a++)
            #pragma unroll
            for(int b=0;b<8;b++)
                #pragma unroll
                for(int c=0;c<4;c++) acc[a][b][c]=0.f;
        for(int dc=0;dc<4;dc++){
            int s=kt*4+dc;
            __syncthreads();
            if(s+1<64){
                int ns=s+1, nk=ns>>2, nd=ns&3, nb=ns&1;
                #pragma unroll
                for(int j=0;j<4;j++){ int id=j*256+tid; int row=id>>3, c=id&7;
                    CPA(sb+SEO+nb*18432+row*144+c*16,
                        g_emb_h+(((long)(nk*128+row))<<8)+nd*64+c*8); }
            }
            CPC(); CPW1();
            __syncthreads();
            uint32_t ebu = sb + SEO + (s&1)*18432;
            #pragma unroll
            for(int ks=0;ks<4;ks++){
                uint32_t ah[2][4];
                #pragma unroll
                for(int mt=0;mt<2;mt++){
                    uint32_t aa = sb + (wm*32+mt*16+lrow)*528 + dc*128 + ks*32 + lkoff;
                    LDSM4(ah[mt][0],ah[mt][1],ah[mt][2],ah[mt][3], aa);
                }
                #pragma unroll
                for(int p=0;p<4;p++){
                    uint32_t ba = ebu + (wn*64+p*16+lrow)*144 + ks*32 + lkoff;
                    uint32_t h0,h1,h2,h3;
                    LDSM4(h0,h1,h2,h3, ba);
                    #pragma unroll
                    for(int mt=0;mt<2;mt++){
                        MMA(acc[mt][2*p],   ah[mt], h0, h2);
                        MMA(acc[mt][2*p+1], ah[mt], h1, h3);
                    }
                }
            }
        }
        #pragma unroll
        for(int nt=0;nt<8;nt++){
            int kb = wn*64 + nt*8 + lc*2;
            float hea = she2all[kt*128+kb], heb = she2all[kt*128+kb+1];
            int k0 = kt*128 + kb;
            #pragma unroll
            for(int mt=0;mt<2;mt++)
                #pragma unroll
                for(int h=0;h<2;h++){
                    int idx=mt*2+h;
                    float v0 = acc[mt][nt][2*h+0]-hea;
                    float v1 = acc[mt][nt][2*h+1]-heb;
                    if(v0>b1v[idx]){ b2v[idx]=b1v[idx]; b1v[idx]=v0; bkv[idx]=k0; }
                    else if(v0>b2v[idx]) b2v[idx]=v0;
                    if(v1>b1v[idx]){ b2v[idx]=b1v[idx]; b1v[idx]=v1; bkv[idx]=k0+1; }
                    else if(v1>b2v[idx]) b2v[idx]=v1;
                }
        }
    }
    #pragma unroll
    for(int off=1;off<4;off<<=1)
        #pragma unroll
        for(int i=0;i<4;i++){
            float ob1=__shfl_xor_sync(0xffffffffu,b1v[i],off);
            float ob2=__shfl_xor_sync(0xffffffffu,b2v[i],off);
            int obk=__shfl_xor_sync(0xffffffffu,bkv[i],off);
            if(ob1>b1v[i]){ b2v[i]=fmaxf(b1v[i],ob2); b1v[i]=ob1; bkv[i]=obk; }
            else b2v[i]=fmaxf(b2v[i],ob1);
        }
    if(wn==1 && lc==0){
        #pragma unroll
        for(int i=0;i<4;i++){ int r=wm*32+(i>>1)*16+(i&1)*8+lr; sb1[r]=b1v[i]; sb2[r]=b2v[i]; sk[r]=bkv[i]; }
    }
    __syncthreads();
    if(wn==0 && lc==0){
        #pragma unroll
        for(int i=0;i<4;i++){
            int r=wm*32+(i>>1)*16+(i&1)*8+lr;
            float ob1=sb1[r], ob2=sb2[r]; int obk=sk[r];
            if(ob1>b1v[i]){ b2v[i]=fmaxf(b1v[i],ob2); b1v[i]=ob1; bkv[i]=obk; }
            else b2v[i]=fmaxf(b2v[i],ob1);
            int row=row0+r;
            g_codes[row]=bkv[i];
            if(b1v[i]-b2v[i] < THRESH_M){ int p=atomicAdd(&g_nflag,1); g_flag[p]=row; }
        }
    }
}

// ---------- recheck: init keys, 4-way k-sliced exact fp32, finalize ----------
__global__ void recheck_init_kernel(){
    int i=blockIdx.x*256+threadIdx.x;
    if(i<g_nflag) g_best[g_flag[i]]=~0ull;
}

__global__ void __launch_bounds__(256,1) recheck_kernel(const float* __restrict__ x){
    extern __shared__ char smem[];
    float* xs  = (float*)smem;               // [256][32]
    float* es  = xs + 256*32;                // [128][33]
    float* rv  = es + 128*33;                // [32 ty][32 row]
    int*   rk  = (int*)(rv + 32*32);
    float* she = (float*)(rk + 32*32);       // [128]
    int*  srows= (int*)(she + 128);          // [32]
    int tid=threadIdx.x, tx=tid&7, ty=tid>>3;
    int ksl=blockIdx.y;
    int n=g_nflag;
    for(int base=blockIdx.x*32; base<n; base+=gridDim.x*32){
        int cnt=min(32,n-base);
        if(tid<32) srows[tid]=g_flag[base+min(tid,cnt-1)];
        __syncthreads();
        for(int r=0;r<32;r++){ int i=tid&31; int d=(tid>>5)+(r<<3);
            int row=srows[i]; int b=row>>12,t=row&4095;
            xs[d*32+i]=x[(((long)(b*PD+d))<<12)+t]; }
        __syncthreads();
        float accr[4][4];
        for(int kt=0;kt<4;kt++){
            int k0 = ksl*512 + kt*128;
            if(tid<128) she[tid]=g_he2[k0+tid];
            #pragma unroll
            for(int i=0;i<4;i++)
                #pragma unroll
                for(int j=0;j<4;j++) accr[i][j]=0.f;
            for(int dcB=0;dcB<8;dcB++){
                __syncthreads();
                #pragma unroll
                for(int r=0;r<16;r++){ int i=tid+r*256; es[(i>>5)*33+(i&31)]=g_emb[(k0+(i>>5))*PD+dcB*32+(i&31)]; }
                __syncthreads();
                #pragma unroll
                for(int d=0;d<32;d++){
                    float4 xv=*(const float4*)&xs[(dcB*32+d)*32+tx*4];
                    float xr[4]={xv.x,xv.y,xv.z,xv.w};
                    #pragma unroll
                    for(int j=0;j<4;j++){ float e=es[(ty*4+j)*33+d];
                        #pragma unroll
                        for(int i=0;i<4;i++) accr[i][j]=fmaf(xr[i],e,accr[i][j]); }
                }
            }
            __syncthreads();
            #pragma unroll
            for(int i=0;i<4;i++){
                float bb=-3.4e38f; int bk=1<<30;
                #pragma unroll
                for(int j=0;j<4;j++){ int k=k0+ty*4+j; float v=accr[i][j]-she[ty*4+j];
                    if(v>bb||(v==bb&&k<bk)){ bb=v; bk=k; } }
                if(kt==0){ rv[ty*32+tx*4+i]=bb; rk[ty*32+tx*4+i]=bk; }
                else { float ov=rv[ty*32+tx*4+i]; int ok=rk[ty*32+tx*4+i];
                       if(bb>ov||(bb==ov&&bk<ok)){ rv[ty*32+tx*4+i]=bb; rk[ty*32+tx*4+i]=bk; } }
            }
        }
        __syncthreads();
        if(tid<32){
            float bv=rv[tid]; int bk=rk[tid];
            #pragma unroll
            for(int y=1;y<32;y++){ float v=rv[y*32+tid]; int kk=rk[y*32+tid];
                if(v>bv||(v==bv&&kk<bk)){ bv=v; bk=kk; } }
            if(tid<cnt){
                float s=-bv;
                uint32_t bits=__float_as_uint(s);
                uint32_t ord = bits ^ ((bits>>31) ? 0xFFFFFFFFu : 0x80000000u);
                unsigned long long key = ((unsigned long long)ord<<32) | (uint32_t)bk;
                atomicMin(&g_best[srows[tid]], key);
            }
        }
        __syncthreads();
    }
}

__global__ void recheck_final_kernel(){
    int i=blockIdx.x*256+threadIdx.x;
    if(i<g_nflag){ int row=g_flag[i]; g_codes[row]=(int)(g_best[row]&0xFFFFFFFFull); }
}

// ---------- outputs ----------
__global__ void emit_codes_f_kernel(float* o){ int i=blockIdx.x*256+threadIdx.x; o[i]=(float)g_codes[i]; }
__global__ void emit_codes_i_kernel(int* o){ int i=blockIdx.x*256+threadIdx.x; o[i]=g_codes[i]; }
__global__ void decode_kernel(float* __restrict__ dec){
    long idx=(long)blockIdx.x*256+threadIdx.x;
    int t=(int)(idx&4095), d=(int)((idx>>12)&255), b=(int)(idx>>20);
    dec[idx]=g_emb[g_codes[b*PT+t]*PD+d];
}

extern "C" void kernel_launch(void* const* d_in, const int* in_sizes, int n_in,
                              void* d_out, int out_size){
    const float* x=(const float*)d_in[0];
    const float* esum=(const float*)d_in[1];
    const float* cu=(const float*)d_in[2];

    prep_emb_kernel<<<PK,256>>>(esum,cu);
    prep_x_kernel<<<dim3(64,4,16),256>>>(x);

    cudaFuncSetAttribute(argmin_mma_kernel,cudaFuncAttributeMaxDynamicSharedMemorySize,SMEMB);
    cudaFuncSetAttribute(recheck_kernel,cudaFuncAttributeMaxDynamicSharedMemorySize,65536);
    argmin_mma_kernel<<<PBT/128,256,SMEMB>>>();
    recheck_init_kernel<<<PBT/256,256>>>();
    recheck_kernel<<<dim3(192,4),256,65536>>>(x);
    recheck_final_kernel<<<PBT/256,256>>>();

    float* codes_out=nullptr; float* dec_out=nullptr; bool ci=false;
    if(out_size==PBT+NDEC){ codes_out=(float*)d_out; dec_out=(float*)d_out+PBT; }
    else if(out_size==NDEC){ dec_out=(float*)d_out; }
    else if(out_size==PBT){ ci=true; }
    else { codes_out=(float*)d_out; if(out_size>=PBT+NDEC) dec_out=(float*)d_out+PBT; }

    if(codes_out) emit_codes_f_kernel<<<PBT/256,256>>>(codes_out);
    if(ci)        emit_codes_i_kernel<<<PBT/256,256>>>((int*)d_out);
    if(dec_out)   decode_kernel<<<NDEC/256,256>>>(dec_out);
}

// round 9
// speedup vs baseline: 3.1541x; 1.1122x over previous
#include <cuda_runtime.h>
#include <cuda_fp16.h>
#include <cstdint>

#define PB 16
#define PD 256
#define PT 4096
#define PK 2048
#define PBT (PB*PT)
#define NDEC (PB*PD*PT)
#define EPSV 1e-5f
#define THRESH_M 0.08f

__device__ float g_emb[PK*PD];
__device__ float g_he2[PK];
__device__ int   g_codes[PBT];
__device__ __half g_x_h[(long)PBT*PD];
__device__ __half g_emb_h[PK*PD];
__device__ int g_flag[PBT];
__device__ int g_nflag;
__device__ unsigned long long g_best[PBT];

__device__ __forceinline__ uint32_t smem_u32(const void* p){
    uint32_t a; asm("{ .reg .u64 t; cvta.to.shared.u64 t, %1; cvt.u32.u64 %0, t; }":"=r"(a):"l"(p)); return a; }
#define CPA(dst,src) asm volatile("cp.async.cg.shared.global [%0],[%1],16;"::"r"(dst),"l"(src):"memory")
#define CPC() asm volatile("cp.async.commit_group;":::"memory")
#define CPW1() asm volatile("cp.async.wait_group 1;":::"memory")
#define MMA(d,a,b0,b1) asm volatile( \
  "mma.sync.aligned.m16n8k16.row.col.f32.f16.f16.f32 {%0,%1,%2,%3},{%4,%5,%6,%7},{%8,%9},{%0,%1,%2,%3};" \
  : "+f"((d)[0]),"+f"((d)[1]),"+f"((d)[2]),"+f"((d)[3]) \
  : "r"((a)[0]),"r"((a)[1]),"r"((a)[2]),"r"((a)[3]),"r"(b0),"r"(b1))
#define LDSM4(r0,r1,r2,r3,addr) asm volatile( \
  "ldmatrix.sync.aligned.m8n8.x4.shared.b16 {%0,%1,%2,%3},[%4];" \
  : "=r"(r0),"=r"(r1),"=r"(r2),"=r"(r3) : "r"(addr))

// ---------- prep ----------
__global__ void prep_emb_kernel(const float* __restrict__ es, const float* __restrict__ cu){
    int k=blockIdx.x, d=threadIdx.x;
    if(k==0 && d==0) g_nflag=0;
    float v = __fdiv_rn(es[k*PD+d], fmaxf(cu[k], EPSV));
    g_emb[k*PD+d]=v;
    float cl = fminf(fmaxf(v,-60000.f),60000.f);   // fp16-safe clamp
    g_emb_h[k*PD+d]=__float2half_rn(cl);
    __shared__ float red[256];
    red[d]=v*v; __syncthreads();
    #pragma unroll
    for(int s=128;s>0;s>>=1){ if(d<s) red[d]+=red[d+s]; __syncthreads(); }
    if(d==0) g_he2[k]=0.5f*red[0];
}

__global__ void prep_x_kernel(const float* __restrict__ x){
    __shared__ float sm[64][65];
    int t0=blockIdx.x*64, d0=blockIdx.y*64, b=blockIdx.z, tid=threadIdx.x;
    #pragma unroll
    for(int r=0;r<16;r++){ int i=tid+r*256; sm[i>>6][i&63] = x[((long)(b*PD+d0+(i>>6)))*PT + t0+(i&63)]; }
    __syncthreads();
    #pragma unroll
    for(int r=0;r<16;r++){
        int i=tid+r*256, t=i>>6, d=i&63;
        long o=(long)(b*PT+t0+t)*PD + d0+d;
        g_x_h[o]=__float2half_rn(sm[d][t]);
    }
}

// ---------- main: fp16 HMMA + fused argmin ----------
#define SEO 67584
#define SHE 104448
#define SRD 112640
#define SMEMB 114176

__global__ void __launch_bounds__(256,1)
argmin_mma_kernel(){
    extern __shared__ char smem[];
    uint32_t sb = smem_u32(smem);
    const int tid=threadIdx.x, lane=tid&31, wid=tid>>5;
    const int wm=wid&3, wn=wid>>2, lr=lane>>2, lc=lane&3;
    const int row0=blockIdx.x*128;
    const int lrow=lane&15, lkoff=(lane>>4)*16;
    float* she2all=(float*)(smem+SHE);
    float* sb1=(float*)(smem+SRD); float* sb2=sb1+128; int* sk=(int*)(sb2+128);

    #pragma unroll 4
    for(int r=0;r<16;r++){ int id=r*256+tid; int row=id>>5, c=id&31;
        CPA(sb+row*528+c*16, g_x_h+(((long)(row0+row))<<8)+c*8); }
    CPC();
    #pragma unroll
    for(int j=0;j<4;j++){ int id=j*256+tid; int row=id>>3, c=id&7;
        CPA(sb+SEO+row*144+c*16, g_emb_h+((long)row<<8)+c*8); }
    CPC();
    #pragma unroll
    for(int j=0;j<8;j++) she2all[j*256+tid]=g_he2[j*256+tid];

    float b1v[4], b2v[4]; int bkv[4];
    #pragma unroll
    for(int i=0;i<4;i++){ b1v[i]=-3.4e38f; b2v[i]=-3.4e38f; bkv[i]=0; }

    for(int kt=0;kt<16;kt++){
        float acc[2][8][4];
        #pragma unroll
        for(int a=0;a<2;a++)
            #pragma unroll
            for(int b=0;b<8;b++)
                #pragma unroll
                for(int c=0;c<4;c++) acc[a][b][c]=0.f;
        for(int dc=0;dc<4;dc++){
            int s=kt*4+dc;
            __syncthreads();
            if(s+1<64){
                int ns=s+1, nk=ns>>2, nd=ns&3, nb=ns&1;
                #pragma unroll
                for(int j=0;j<4;j++){ int id=j*256+tid; int row=id>>3, c=id&7;
                    CPA(sb+SEO+nb*18432+row*144+c*16,
                        g_emb_h+(((long)(nk*128+row))<<8)+nd*64+c*8); }
            }
            CPC(); CPW1();
            __syncthreads();
            uint32_t ebu = sb + SEO + (s&1)*18432;
            #pragma unroll
            for(int ks=0;ks<4;ks++){
                uint32_t ah[2][4];
                #pragma unroll
                for(int mt=0;mt<2;mt++){
                    uint32_t aa = sb + (wm*32+mt*16+lrow)*528 + dc*128 + ks*32 + lkoff;
                    LDSM4(ah[mt][0],ah[mt][1],ah[mt][2],ah[mt][3], aa);
                }
                #pragma unroll
                for(int p=0;p<4;p++){
                    uint32_t ba = ebu + (wn*64+p*16+lrow)*144 + ks*32 + lkoff;
                    uint32_t h0,h1,h2,h3;
                    LDSM4(h0,h1,h2,h3, ba);
                    #pragma unroll
                    for(int mt=0;mt<2;mt++){
                        MMA(acc[mt][2*p],   ah[mt], h0, h2);
                        MMA(acc[mt][2*p+1], ah[mt], h1, h3);
                    }
                }
            }
        }
        #pragma unroll
        for(int nt=0;nt<8;nt++){
            int kb = wn*64 + nt*8 + lc*2;
            float hea = she2all[kt*128+kb], heb = she2all[kt*128+kb+1];
            int k0 = kt*128 + kb;
            #pragma unroll
            for(int mt=0;mt<2;mt++)
                #pragma unroll
                for(int h=0;h<2;h++){
                    int idx=mt*2+h;
                    float v0 = acc[mt][nt][2*h+0]-hea;
                    float v1 = acc[mt][nt][2*h+1]-heb;
                    if(v0>b1v[idx]){ b2v[idx]=b1v[idx]; b1v[idx]=v0; bkv[idx]=k0; }
                    else if(v0>b2v[idx]) b2v[idx]=v0;
                    if(v1>b1v[idx]){ b2v[idx]=b1v[idx]; b1v[idx]=v1; bkv[idx]=k0+1; }
                    else if(v1>b2v[idx]) b2v[idx]=v1;
                }
        }
    }
    #pragma unroll
    for(int off=1;off<4;off<<=1)
        #pragma unroll
        for(int i=0;i<4;i++){
            float ob1=__shfl_xor_sync(0xffffffffu,b1v[i],off);
            float ob2=__shfl_xor_sync(0xffffffffu,b2v[i],off);
            int obk=__shfl_xor_sync(0xffffffffu,bkv[i],off);
            if(ob1>b1v[i]){ b2v[i]=fmaxf(b1v[i],ob2); b1v[i]=ob1; bkv[i]=obk; }
            else b2v[i]=fmaxf(b2v[i],ob1);
        }
    if(wn==1 && lc==0){
        #pragma unroll
        for(int i=0;i<4;i++){ int r=wm*32+(i>>1)*16+(i&1)*8+lr; sb1[r]=b1v[i]; sb2[r]=b2v[i]; sk[r]=bkv[i]; }
    }
    __syncthreads();
    if(wn==0 && lc==0){
        #pragma unroll
        for(int i=0;i<4;i++){
            int r=wm*32+(i>>1)*16+(i&1)*8+lr;
            float ob1=sb1[r], ob2=sb2[r]; int obk=sk[r];
            if(ob1>b1v[i]){ b2v[i]=fmaxf(b1v[i],ob2); b1v[i]=ob1; bkv[i]=obk; }
            else b2v[i]=fmaxf(b2v[i],ob1);
            int row=row0+r;
            g_codes[row]=bkv[i];
            if(b1v[i]-b2v[i] < THRESH_M){ int p=atomicAdd(&g_nflag,1); g_flag[p]=row; }
        }
    }
}

// ---------- recheck: init keys, 4-way k-sliced exact fp32, finalize ----------
__global__ void recheck_init_kernel(){
    int i=blockIdx.x*256+threadIdx.x;
    if(i<g_nflag) g_best[g_flag[i]]=~0ull;
}

__global__ void __launch_bounds__(256,1) recheck_kernel(const float* __restrict__ x){
    extern __shared__ char smem[];
    float* xs  = (float*)smem;               // [256][32]
    float* es  = xs + 256*32;                // [128][33]
    float* rv  = es + 128*33;                // [32 ty][32 row]
    int*   rk  = (int*)(rv + 32*32);
    float* she = (float*)(rk + 32*32);       // [128]
    int*  srows= (int*)(she + 128);          // [32]
    int tid=threadIdx.x, tx=tid&7, ty=tid>>3;
    int ksl=blockIdx.y;
    int n=g_nflag;
    for(int base=blockIdx.x*32; base<n; base+=gridDim.x*32){
        int cnt=min(32,n-base);
        if(tid<32) srows[tid]=g_flag[base+min(tid,cnt-1)];
        __syncthreads();
        for(int r=0;r<32;r++){ int i=tid&31; int d=(tid>>5)+(r<<3);
            int row=srows[i]; int b=row>>12,t=row&4095;
            xs[d*32+i]=x[(((long)(b*PD+d))<<12)+t]; }
        __syncthreads();
        float accr[4][4];
        for(int kt=0;kt<4;kt++){
            int k0 = ksl*512 + kt*128;
            if(tid<128) she[tid]=g_he2[k0+tid];
            #pragma unroll
            for(int i=0;i<4;i++)
                #pragma unroll
                for(int j=0;j<4;j++) accr[i][j]=0.f;
            for(int dcB=0;dcB<8;dcB++){
                __syncthreads();
                #pragma unroll
                for(int r=0;r<16;r++){ int i=tid+r*256; es[(i>>5)*33+(i&31)]=g_emb[(k0+(i>>5))*PD+dcB*32+(i&31)]; }
                __syncthreads();
                #pragma unroll
                for(int d=0;d<32;d++){
                    float4 xv=*(const float4*)&xs[(dcB*32+d)*32+tx*4];
                    float xr[4]={xv.x,xv.y,xv.z,xv.w};
                    #pragma unroll
                    for(int j=0;j<4;j++){ float e=es[(ty*4+j)*33+d];
                        #pragma unroll
                        for(int i=0;i<4;i++) accr[i][j]=fmaf(xr[i],e,accr[i][j]); }
                }
            }
            __syncthreads();
            #pragma unroll
            for(int i=0;i<4;i++){
                float bb=-3.4e38f; int bk=1<<30;
                #pragma unroll
                for(int j=0;j<4;j++){ int k=k0+ty*4+j; float v=accr[i][j]-she[ty*4+j];
                    if(v>bb||(v==bb&&k<bk)){ bb=v; bk=k; } }
                if(kt==0){ rv[ty*32+tx*4+i]=bb; rk[ty*32+tx*4+i]=bk; }
                else { float ov=rv[ty*32+tx*4+i]; int ok=rk[ty*32+tx*4+i];
                       if(bb>ov||(bb==ov&&bk<ok)){ rv[ty*32+tx*4+i]=bb; rk[ty*32+tx*4+i]=bk; } }
            }
        }
        __syncthreads();
        if(tid<32){
            float bv=rv[tid]; int bk=rk[tid];
            #pragma unroll
            for(int y=1;y<32;y++){ float v=rv[y*32+tid]; int kk=rk[y*32+tid];
                if(v>bv||(v==bv&&kk<bk)){ bv=v; bk=kk; } }
            if(tid<cnt){
                float s=-bv;
                uint32_t bits=__float_as_uint(s);
                uint32_t ord = bits ^ ((bits>>31) ? 0xFFFFFFFFu : 0x80000000u);
                unsigned long long key = ((unsigned long long)ord<<32) | (uint32_t)bk;
                atomicMin(&g_best[srows[tid]], key);
            }
        }
        __syncthreads();
    }
}

__global__ void recheck_final_kernel(){
    int i=blockIdx.x*256+threadIdx.x;
    if(i<g_nflag){ int row=g_flag[i]; g_codes[row]=(int)(g_best[row]&0xFFFFFFFFull); }
}

// ---------- outputs ----------
__global__ void emit_codes_f_kernel(float* o){ int i=blockIdx.x*256+threadIdx.x; o[i]=(float)g_codes[i]; }
__global__ void emit_codes_i_kernel(int* o){ int i=blockIdx.x*256+threadIdx.x; o[i]=g_codes[i]; }
__global__ void decode_kernel(float* __restrict__ dec){
    long idx=(long)blockIdx.x*256+threadIdx.x;
    int t=(int)(idx&4095), d=(int)((idx>>12)&255), b=(int)(idx>>20);
    dec[idx]=g_emb[g_codes[b*PT+t]*PD+d];
}

extern "C" void kernel_launch(void* const* d_in, const int* in_sizes, int n_in,
                              void* d_out, int out_size){
    const float* x=(const float*)d_in[0];
    const float* esum=(const float*)d_in[1];
    const float* cu=(const float*)d_in[2];

    prep_emb_kernel<<<PK,256>>>(esum,cu);
    prep_x_kernel<<<dim3(64,4,16),256>>>(x);

    cudaFuncSetAttribute(argmin_mma_kernel,cudaFuncAttributeMaxDynamicSharedMemorySize,SMEMB);
    cudaFuncSetAttribute(recheck_kernel,cudaFuncAttributeMaxDynamicSharedMemorySize,65536);
    argmin_mma_kernel<<<PBT/128,256,SMEMB>>>();
    recheck_init_kernel<<<PBT/256,256>>>();
    recheck_kernel<<<dim3(192,4),256,65536>>>(x);
    recheck_final_kernel<<<PBT/256,256>>>();

    float* codes_out=nullptr; float* dec_out=nullptr; bool ci=false;
    if(out_size==PBT+NDEC){ codes_out=(float*)d_out; dec_out=(float*)d_out+PBT; }
    else if(out_size==NDEC){ dec_out=(float*)d_out; }
    else if(out_size==PBT){ ci=true; }
    else { codes_out=(float*)d_out; if(out_size>=PBT+NDEC) dec_out=(float*)d_out+PBT; }

    if(codes_out) emit_codes_f_kernel<<<PBT/256,256>>>(codes_out);
    if(ci)        emit_codes_i_kernel<<<PBT/256,256>>>((int*)d_out);
    if(dec_out)   decode_kernel<<<NDEC/256,256>>>(dec_out);
}

// round 10
// speedup vs baseline: 3.8308x; 1.2146x over previous
#include <cuda_runtime.h>
#include <cuda_fp16.h>
#include <cstdint>

#define PB 16
#define PD 256
#define PT 4096
#define PK 2048
#define PBT (PB*PT)
#define NDEC (PB*PD*PT)
#define EPSV 1e-5f
#define THRESH_M 0.08f

__device__ float g_emb[PK*PD];
__device__ float g_he2[PK];
__device__ int   g_codes[PBT];
__device__ __half g_x_h[(long)PBT*PD];
__device__ __half g_emb_h[PK*PD];
__device__ int g_flag[PBT];
__device__ int g_nflag;
__device__ unsigned long long g_best[PBT];

__device__ __forceinline__ uint32_t smem_u32(const void* p){
    uint32_t a; asm("{ .reg .u64 t; cvta.to.shared.u64 t, %1; cvt.u32.u64 %0, t; }":"=r"(a):"l"(p)); return a; }
#define CPA(dst,src) asm volatile("cp.async.cg.shared.global [%0],[%1],16;"::"r"(dst),"l"(src):"memory")
#define CPC() asm volatile("cp.async.commit_group;":::"memory")
#define CPW1() asm volatile("cp.async.wait_group 1;":::"memory")
#define MMA(d,a,b0,b1) asm volatile( \
  "mma.sync.aligned.m16n8k16.row.col.f32.f16.f16.f32 {%0,%1,%2,%3},{%4,%5,%6,%7},{%8,%9},{%0,%1,%2,%3};" \
  : "+f"((d)[0]),"+f"((d)[1]),"+f"((d)[2]),"+f"((d)[3]) \
  : "r"((a)[0]),"r"((a)[1]),"r"((a)[2]),"r"((a)[3]),"r"(b0),"r"(b1))
#define LDSM4(r0,r1,r2,r3,addr) asm volatile( \
  "ldmatrix.sync.aligned.m8n8.x4.shared.b16 {%0,%1,%2,%3},[%4];" \
  : "=r"(r0),"=r"(r1),"=r"(r2),"=r"(r3) : "r"(addr))

// ---------- prep ----------
__global__ void prep_emb_kernel(const float* __restrict__ es, const float* __restrict__ cu){
    int k=blockIdx.x, d=threadIdx.x;
    if(k==0 && d==0) g_nflag=0;
    float v = __fdiv_rn(es[k*PD+d], fmaxf(cu[k], EPSV));
    g_emb[k*PD+d]=v;
    float cl = fminf(fmaxf(v,-60000.f),60000.f);
    g_emb_h[k*PD+d]=__float2half_rn(cl);
    __shared__ float red[256];
    red[d]=v*v; __syncthreads();
    #pragma unroll
    for(int s=128;s>0;s>>=1){ if(d<s) red[d]+=red[d+s]; __syncthreads(); }
    if(d==0) g_he2[k]=0.5f*red[0];
}

__global__ void prep_x_kernel(const float* __restrict__ x){
    __shared__ float sm[64][65];
    int t0=blockIdx.x*64, d0=blockIdx.y*64, b=blockIdx.z, tid=threadIdx.x;
    #pragma unroll
    for(int r=0;r<16;r++){ int i=tid+r*256; sm[i>>6][i&63] = x[((long)(b*PD+d0+(i>>6)))*PT + t0+(i&63)]; }
    __syncthreads();
    #pragma unroll
    for(int r=0;r<16;r++){
        int i=tid+r*256, t=i>>6, d=i&63;
        long o=(long)(b*PT+t0+t)*PD + d0+d;
        g_x_h[o]=__float2half_rn(sm[d][t]);
    }
}

// ---------- main: fp16 HMMA + fused argmin, 2 CTAs/SM ----------
// smem: A 128x528 = 67584 | B 2x18432 @67584 | red 1536 @104448 -> 105984
#define SEO 67584
#define SRD 104448
#define SMEMB 105984

__global__ void __launch_bounds__(256,2)
argmin_mma_kernel(){
    extern __shared__ char smem[];
    uint32_t sb = smem_u32(smem);
    const int tid=threadIdx.x, lane=tid&31, wid=tid>>5;
    const int wm=wid&3, wn=wid>>2, lr=lane>>2, lc=lane&3;
    const int row0=blockIdx.x*128;
    const int lrow=lane&15, lkoff=(lane>>4)*16;
    float* sb1=(float*)(smem+SRD); float* sb2=sb1+128; int* sk=(int*)(sb2+128);

    #pragma unroll 4
    for(int r=0;r<16;r++){ int id=r*256+tid; int row=id>>5, c=id&31;
        CPA(sb+row*528+c*16, g_x_h+(((long)(row0+row))<<8)+c*8); }
    CPC();
    #pragma unroll
    for(int j=0;j<4;j++){ int id=j*256+tid; int row=id>>3, c=id&7;
        CPA(sb+SEO+row*144+c*16, g_emb_h+((long)row<<8)+c*8); }
    CPC();

    float b1v[4], b2v[4]; int bkv[4];
    #pragma unroll
    for(int i=0;i<4;i++){ b1v[i]=-3.4e38f; b2v[i]=-3.4e38f; bkv[i]=0; }

    for(int kt=0;kt<16;kt++){
        float acc[2][8][4];
        #pragma unroll
        for(int a=0;a<2;a++)
            #pragma unroll
            for(int b=0;b<8;b++)
                #pragma unroll
                for(int c=0;c<4;c++) acc[a][b][c]=0.f;
        for(int dc=0;dc<4;dc++){
            int s=kt*4+dc;
            __syncthreads();
            if(s+1<64){
                int ns=s+1, nk=ns>>2, nd=ns&3, nb=ns&1;
                #pragma unroll
                for(int j=0;j<4;j++){ int id=j*256+tid; int row=id>>3, c=id&7;
                    CPA(sb+SEO+nb*18432+row*144+c*16,
                        g_emb_h+(((long)(nk*128+row))<<8)+nd*64+c*8); }
            }
            CPC(); CPW1();
            __syncthreads();
            uint32_t ebu = sb + SEO + (s&1)*18432;
            #pragma unroll
            for(int ks=0;ks<4;ks++){
                uint32_t ah[2][4];
                #pragma unroll
                for(int mt=0;mt<2;mt++){
                    uint32_t aa = sb + (wm*32+mt*16+lrow)*528 + dc*128 + ks*32 + lkoff;
                    LDSM4(ah[mt][0],ah[mt][1],ah[mt][2],ah[mt][3], aa);
                }
                #pragma unroll
                for(int p=0;p<4;p++){
                    uint32_t ba = ebu + (wn*64+p*16+lrow)*144 + ks*32 + lkoff;
                    uint32_t h0,h1,h2,h3;
                    LDSM4(h0,h1,h2,h3, ba);
                    #pragma unroll
                    for(int mt=0;mt<2;mt++){
                        MMA(acc[mt][2*p],   ah[mt], h0, h2);
                        MMA(acc[mt][2*p+1], ah[mt], h1, h3);
                    }
                }
            }
        }
        // epilogue: he2 straight from L2 (codebook-resident, 8KB)
        #pragma unroll
        for(int nt=0;nt<8;nt++){
            int kb = wn*64 + nt*8 + lc*2;
            int k0 = kt*128 + kb;
            float hea = __ldg(&g_he2[k0]), heb = __ldg(&g_he2[k0+1]);
            #pragma unroll
            for(int mt=0;mt<2;mt++)
                #pragma unroll
                for(int h=0;h<2;h++){
                    int idx=mt*2+h;
                    float v0 = acc[mt][nt][2*h+0]-hea;
                    float v1 = acc[mt][nt][2*h+1]-heb;
                    if(v0>b1v[idx]){ b2v[idx]=b1v[idx]; b1v[idx]=v0; bkv[idx]=k0; }
                    else if(v0>b2v[idx]) b2v[idx]=v0;
                    if(v1>b1v[idx]){ b2v[idx]=b1v[idx]; b1v[idx]=v1; bkv[idx]=k0+1; }
                    else if(v1>b2v[idx]) b2v[idx]=v1;
                }
        }
    }
    #pragma unroll
    for(int off=1;off<4;off<<=1)
        #pragma unroll
        for(int i=0;i<4;i++){
            float ob1=__shfl_xor_sync(0xffffffffu,b1v[i],off);
            float ob2=__shfl_xor_sync(0xffffffffu,b2v[i],off);
            int obk=__shfl_xor_sync(0xffffffffu,bkv[i],off);
            if(ob1>b1v[i]){ b2v[i]=fmaxf(b1v[i],ob2); b1v[i]=ob1; bkv[i]=obk; }
            else b2v[i]=fmaxf(b2v[i],ob1);
        }
    if(wn==1 && lc==0){
        #pragma unroll
        for(int i=0;i<4;i++){ int r=wm*32+(i>>1)*16+(i&1)*8+lr; sb1[r]=b1v[i]; sb2[r]=b2v[i]; sk[r]=bkv[i]; }
    }
    __syncthreads();
    if(wn==0 && lc==0){
        #pragma unroll
        for(int i=0;i<4;i++){
            int r=wm*32+(i>>1)*16+(i&1)*8+lr;
            float ob1=sb1[r], ob2=sb2[r]; int obk=sk[r];
            if(ob1>b1v[i]){ b2v[i]=fmaxf(b1v[i],ob2); b1v[i]=ob1; bkv[i]=obk; }
            else b2v[i]=fmaxf(b2v[i],ob1);
            int row=row0+r;
            g_codes[row]=bkv[i];
            if(b1v[i]-b2v[i] < THRESH_M){ int p=atomicAdd(&g_nflag,1); g_flag[p]=row; }
        }
    }
}

// ---------- recheck ----------
__global__ void recheck_init_kernel(){
    int i=blockIdx.x*256+threadIdx.x;
    if(i<g_nflag) g_best[g_flag[i]]=~0ull;
}

__global__ void __launch_bounds__(256,1) recheck_kernel(const float* __restrict__ x){
    extern __shared__ char smem[];
    float* xs  = (float*)smem;
    float* es  = xs + 256*32;
    float* rv  = es + 128*33;
    int*   rk  = (int*)(rv + 32*32);
    float* she = (float*)(rk + 32*32);
    int*  srows= (int*)(she + 128);
    int tid=threadIdx.x, tx=tid&7, ty=tid>>3;
    int ksl=blockIdx.y;
    int n=g_nflag;
    for(int base=blockIdx.x*32; base<n; base+=gridDim.x*32){
        int cnt=min(32,n-base);
        if(tid<32) srows[tid]=g_flag[base+min(tid,cnt-1)];
        __syncthreads();
        for(int r=0;r<32;r++){ int i=tid&31; int d=(tid>>5)+(r<<3);
            int row=srows[i]; int b=row>>12,t=row&4095;
            xs[d*32+i]=x[(((long)(b*PD+d))<<12)+t]; }
        __syncthreads();
        float accr[4][4];
        for(int kt=0;kt<4;kt++){
            int k0 = ksl*512 + kt*128;
            if(tid<128) she[tid]=g_he2[k0+tid];
            #pragma unroll
            for(int i=0;i<4;i++)
                #pragma unroll
                for(int j=0;j<4;j++) accr[i][j]=0.f;
            for(int dcB=0;dcB<8;dcB++){
                __syncthreads();
                #pragma unroll
                for(int r=0;r<16;r++){ int i=tid+r*256; es[(i>>5)*33+(i&31)]=g_emb[(k0+(i>>5))*PD+dcB*32+(i&31)]; }
                __syncthreads();
                #pragma unroll
                for(int d=0;d<32;d++){
                    float4 xv=*(const float4*)&xs[(dcB*32+d)*32+tx*4];
                    float xr[4]={xv.x,xv.y,xv.z,xv.w};
                    #pragma unroll
                    for(int j=0;j<4;j++){ float e=es[(ty*4+j)*33+d];
                        #pragma unroll
                        for(int i=0;i<4;i++) accr[i][j]=fmaf(xr[i],e,accr[i][j]); }
                }
            }
            __syncthreads();
            #pragma unroll
            for(int i=0;i<4;i++){
                float bb=-3.4e38f; int bk=1<<30;
                #pragma unroll
                for(int j=0;j<4;j++){ int k=k0+ty*4+j; float v=accr[i][j]-she[ty*4+j];
                    if(v>bb||(v==bb&&k<bk)){ bb=v; bk=k; } }
                if(kt==0){ rv[ty*32+tx*4+i]=bb; rk[ty*32+tx*4+i]=bk; }
                else { float ov=rv[ty*32+tx*4+i]; int ok=rk[ty*32+tx*4+i];
                       if(bb>ov||(bb==ov&&bk<ok)){ rv[ty*32+tx*4+i]=bb; rk[ty*32+tx*4+i]=bk; } }
            }
        }
        __syncthreads();
        if(tid<32){
            float bv=rv[tid]; int bk=rk[tid];
            #pragma unroll
            for(int y=1;y<32;y++){ float v=rv[y*32+tid]; int kk=rk[y*32+tid];
                if(v>bv||(v==bv&&kk<bk)){ bv=v; bk=kk; } }
            if(tid<cnt){
                float s=-bv;
                uint32_t bits=__float_as_uint(s);
                uint32_t ord = bits ^ ((bits>>31) ? 0xFFFFFFFFu : 0x80000000u);
                unsigned long long key = ((unsigned long long)ord<<32) | (uint32_t)bk;
                atomicMin(&g_best[srows[tid]], key);
            }
        }
        __syncthreads();
    }
}

__global__ void recheck_final_kernel(){
    int i=blockIdx.x*256+threadIdx.x;
    if(i<g_nflag){ int row=g_flag[i]; g_codes[row]=(int)(g_best[row]&0xFFFFFFFFull); }
}

// ---------- outputs ----------
__global__ void emit_codes_f_kernel(float* o){ int i=blockIdx.x*256+threadIdx.x; o[i]=(float)g_codes[i]; }
__global__ void emit_codes_i_kernel(int* o){ int i=blockIdx.x*256+threadIdx.x; o[i]=g_codes[i]; }
__global__ void decode_kernel(float* __restrict__ dec){
    long idx=(long)blockIdx.x*256+threadIdx.x;
    int t=(int)(idx&4095), d=(int)((idx>>12)&255), b=(int)(idx>>20);
    dec[idx]=g_emb[g_codes[b*PT+t]*PD+d];
}

extern "C" void kernel_launch(void* const* d_in, const int* in_sizes, int n_in,
                              void* d_out, int out_size){
    const float* x=(const float*)d_in[0];
    const float* esum=(const float*)d_in[1];
    const float* cu=(const float*)d_in[2];

    prep_emb_kernel<<<PK,256>>>(esum,cu);
    prep_x_kernel<<<dim3(64,4,16),256>>>(x);

    cudaFuncSetAttribute(argmin_mma_kernel,cudaFuncAttributeMaxDynamicSharedMemorySize,SMEMB);
    cudaFuncSetAttribute(recheck_kernel,cudaFuncAttributeMaxDynamicSharedMemorySize,65536);
    argmin_mma_kernel<<<PBT/128,256,SMEMB>>>();
    recheck_init_kernel<<<PBT/256,256>>>();
    recheck_kernel<<<dim3(192,4),256,65536>>>(x);
    recheck_final_kernel<<<PBT/256,256>>>();

    float* codes_out=nullptr; float* dec_out=nullptr; bool ci=false;
    if(out_size==PBT+NDEC){ codes_out=(float*)d_out; dec_out=(float*)d_out+PBT; }
    else if(out_size==NDEC){ dec_out=(float*)d_out; }
    else if(out_size==PBT){ ci=true; }
    else { codes_out=(float*)d_out; if(out_size>=PBT+NDEC) dec_out=(float*)d_out+PBT; }

    if(codes_out) emit_codes_f_kernel<<<PBT/256,256>>>(codes_out);
    if(ci)        emit_codes_i_kernel<<<PBT/256,256>>>((int*)d_out);
    if(dec_out)   decode_kernel<<<NDEC/256,256>>>(dec_out);
}